// round 2
// baseline (speedup 1.0000x reference)
#include <cuda_runtime.h>
#include <math.h>
#include <stdint.h>

// ---------------- problem constants ----------------
#define BATCH   32
#define HIMG    56
#define WIMG    56
#define CDIM    384
#define NHEAD   12
#define HDIM    32
#define WSZ     7
#define NWIN_N  49            // tokens per window
#define NW_PER  64            // windows per image (8x8)
#define TOK     100352        // 32*3136
#define EPS     1e-5f
#define SCALE   0.17677669529663687f  // 1/sqrt(32)

// ---------------- scratch (device globals; no allocations) ----------------
__device__ float g_h  [(size_t)TOK * 384];    // LN1 + windowed   (154 MB)
__device__ float g_qkv[(size_t)TOK * 1152];   // qkv              (462 MB)
__device__ float g_o  [(size_t)TOK * 384];    // attn out (win order)
__device__ float g_xa [(size_t)TOK * 384];    // x after attn residual (orig order)
__device__ float g_y  [(size_t)TOK * 384];    // LN2 out
__device__ float g_u  [(size_t)TOK * 1536];   // fc1/gelu out     (616 MB)

// window-order row t  <->  original-order row (same map both directions)
__device__ __forceinline__ int winrow_to_orig(int t) {
    int b   = t / 3136;
    int rem = t - b * 3136;
    int w   = rem / 49;
    int n   = rem - w * 49;
    int wr = w >> 3, wc = w & 7;
    int r  = n / 7,  c  = n - r * 7;
    int gh = wr * 7 + r + 3; if (gh >= 56) gh -= 56;
    int gw = wc * 7 + c + 3; if (gw >= 56) gw -= 56;
    return b * 3136 + gh * 56 + gw;
}

// ---------------- LayerNorm (optionally gathering into window order) -------
// grid = TOK blocks, 128 threads. Each thread handles 3 channels.
template<int GATHER>
__global__ void __launch_bounds__(128) ln_kernel(
    const float* __restrict__ x, const float* __restrict__ g,
    const float* __restrict__ b, float* __restrict__ out)
{
    int t   = blockIdx.x;
    int src = GATHER ? winrow_to_orig(t) : t;
    const float* xr = x + (size_t)src * CDIM;
    int tid = threadIdx.x;

    float v0 = xr[tid], v1 = xr[tid + 128], v2 = xr[tid + 256];
    float s  = v0 + v1 + v2;
    float sq = v0 * v0 + v1 * v1 + v2 * v2;

    __shared__ float rs[128], rq[128];
    rs[tid] = s; rq[tid] = sq;
    __syncthreads();
    #pragma unroll
    for (int off = 64; off > 0; off >>= 1) {
        if (tid < off) { rs[tid] += rs[tid + off]; rq[tid] += rq[tid + off]; }
        __syncthreads();
    }
    float mean = rs[0] * (1.0f / CDIM);
    float var  = rq[0] * (1.0f / CDIM) - mean * mean;
    float inv  = rsqrtf(var + EPS);

    float* orow = out + (size_t)t * CDIM;
    orow[tid      ] = (v0 - mean) * inv * g[tid      ] + b[tid      ];
    orow[tid + 128] = (v1 - mean) * inv * g[tid + 128] + b[tid + 128];
    orow[tid + 256] = (v2 - mean) * inv * g[tid + 256] + b[tid + 256];
}

// ---------------- SGEMM 128x128x8, 256 threads, 8x8 per thread -------------
// MODE 0: C = A*B + bias
// MODE 1: C = gelu(A*B + bias)
// MODE 2: C = A*B + bias + res[row]            (same row order)
// MODE 3: C[map(row)] = A*B + bias + res[map(row)]   (window->orig scatter)
template<int MODE>
__global__ void __launch_bounds__(256) sgemm_k(
    const float* __restrict__ A, const float* __restrict__ B,
    const float* __restrict__ bias, const float* __restrict__ res,
    float* __restrict__ C, int N, int K)
{
    __shared__ float As[8][128];
    __shared__ float Bs[8][128];

    int tid = threadIdx.x;
    int tx = tid & 15, ty = tid >> 4;
    int bx = blockIdx.x, by = blockIdx.y;

    // load indices
    int arow = tid >> 1;            // 0..127
    int acol = (tid & 1) * 4;       // 0 or 4
    int brow = tid >> 5;            // 0..7
    int bcol = (tid & 31) * 4;      // 0..124

    const float* Ap = A + (size_t)(by * 128 + arow) * K + acol;
    const float* Bp = B + (size_t)brow * N + bx * 128 + bcol;

    float acc[8][8];
    #pragma unroll
    for (int i = 0; i < 8; i++)
        #pragma unroll
        for (int j = 0; j < 8; j++) acc[i][j] = 0.0f;

    for (int kt = 0; kt < K; kt += 8) {
        float4 av = *(const float4*)Ap;
        float4 bv = *(const float4*)Bp;
        As[acol + 0][arow] = av.x;
        As[acol + 1][arow] = av.y;
        As[acol + 2][arow] = av.z;
        As[acol + 3][arow] = av.w;
        *(float4*)(&Bs[brow][bcol]) = bv;
        __syncthreads();

        #pragma unroll
        for (int k = 0; k < 8; k++) {
            float a[8], bb[8];
            *(float4*)(a)      = *(const float4*)(&As[k][ty * 8]);
            *(float4*)(a + 4)  = *(const float4*)(&As[k][ty * 8 + 4]);
            *(float4*)(bb)     = *(const float4*)(&Bs[k][tx * 8]);
            *(float4*)(bb + 4) = *(const float4*)(&Bs[k][tx * 8 + 4]);
            #pragma unroll
            for (int i = 0; i < 8; i++)
                #pragma unroll
                for (int j = 0; j < 8; j++)
                    acc[i][j] += a[i] * bb[j];
        }
        __syncthreads();
        Ap += 8;
        Bp += (size_t)8 * N;
    }

    int row0 = by * 128 + ty * 8;
    int col0 = bx * 128 + tx * 8;
    float bv[8];
    #pragma unroll
    for (int j = 0; j < 8; j++) bv[j] = bias[col0 + j];

    #pragma unroll
    for (int i = 0; i < 8; i++) {
        int row  = row0 + i;
        int orow = (MODE == 3) ? winrow_to_orig(row) : row;
        size_t cbase = (size_t)orow * N + col0;
        #pragma unroll
        for (int j = 0; j < 8; j++) {
            float v = acc[i][j] + bv[j];
            if (MODE == 1) {
                v = 0.5f * v * (1.0f + erff(v * 0.70710678118654752f));
            } else if (MODE >= 2) {
                v += res[cbase + j];
            }
            C[cbase + j] = v;
        }
    }
}

// ---------------- attention: one block per (window, head) ------------------
// Region boundaries in the shifted image: rows 0..48 -> 0, 49..52 -> 1, 53..55 -> 2
// (slices (0,-WS), (-WS,-SHIFT), (-SHIFT,None) with WS=7, SHIFT=3)
__device__ __forceinline__ int regio(int g) { return g < 49 ? 0 : (g < 53 ? 1 : 2); }

__global__ void __launch_bounds__(256) attn_kernel(
    const float* __restrict__ qkv, const float* __restrict__ bias_table,
    float* __restrict__ o)
{
    int bh   = blockIdx.x;           // 0 .. 2048*12-1
    int wi   = bh / NHEAD;           // global window
    int head = bh - wi * NHEAD;
    int w    = wi & 63;              // window within image
    int tid  = threadIdx.x;

    __shared__ float qs[49][32];
    __shared__ float ks[49][32];
    __shared__ float vs[49][32];
    __shared__ float S [49][49];

    size_t base = (size_t)wi * 49 * 1152 + head * 32;
    for (int e = tid; e < 49 * 32; e += 256) {
        int n = e >> 5, d = e & 31;
        size_t off = base + (size_t)n * 1152 + d;
        qs[n][d] = qkv[off] * SCALE;
        ks[n][d] = qkv[off + 384];
        vs[n][d] = qkv[off + 768];
    }
    __syncthreads();

    int wr = w >> 3, wc = w & 7;
    for (int e = tid; e < 49 * 49; e += 256) {
        int i = e / 49, j = e - i * 49;
        float s = 0.0f;
        #pragma unroll
        for (int d = 0; d < 32; d++) s += qs[i][d] * ks[j][d];

        int ih = i / 7, iw = i - ih * 7;
        int jh = j / 7, jw = j - jh * 7;
        int ridx = (ih - jh + 6) * 13 + (iw - jw + 6);
        s += bias_table[ridx * NHEAD + head];

        int li = regio(wr * 7 + ih) * 3 + regio(wc * 7 + iw);
        int lj = regio(wr * 7 + jh) * 3 + regio(wc * 7 + jw);
        if (li != lj) s -= 100.0f;
        S[i][j] = s;
    }
    __syncthreads();

    if (tid < 49) {
        float mx = -1e30f;
        #pragma unroll 7
        for (int j = 0; j < 49; j++) mx = fmaxf(mx, S[tid][j]);
        float sm = 0.0f;
        #pragma unroll 7
        for (int j = 0; j < 49; j++) {
            float e = __expf(S[tid][j] - mx);
            S[tid][j] = e; sm += e;
        }
        float inv = 1.0f / sm;
        #pragma unroll 7
        for (int j = 0; j < 49; j++) S[tid][j] *= inv;
    }
    __syncthreads();

    for (int e = tid; e < 49 * 32; e += 256) {
        int i = e >> 5, d = e & 31;
        float s = 0.0f;
        #pragma unroll 7
        for (int j = 0; j < 49; j++) s += S[i][j] * vs[j][d];
        o[(size_t)wi * 49 * 384 + (size_t)i * 384 + head * 32 + d] = s;
    }
}

// ---------------- host launch ----------------------------------------------
extern "C" void kernel_launch(void* const* d_in, const int* in_sizes, int n_in,
                              void* d_out, int out_size)
{
    const float* x       = (const float*)d_in[0];
    const float* ln1_g   = (const float*)d_in[1];
    const float* ln1_b   = (const float*)d_in[2];
    const float* qkv_w   = (const float*)d_in[3];
    const float* qkv_b   = (const float*)d_in[4];
    const float* proj_w  = (const float*)d_in[5];
    const float* proj_b  = (const float*)d_in[6];
    const float* bias_tb = (const float*)d_in[7];
    const float* ln2_g   = (const float*)d_in[8];
    const float* ln2_b   = (const float*)d_in[9];
    const float* fc1_w   = (const float*)d_in[10];
    const float* fc1_b   = (const float*)d_in[11];
    const float* fc2_w   = (const float*)d_in[12];
    const float* fc2_b   = (const float*)d_in[13];
    float*       out     = (float*)d_out;

    float *ph, *pqkv, *po, *pxa, *py, *pu;
    cudaGetSymbolAddress((void**)&ph,   g_h);
    cudaGetSymbolAddress((void**)&pqkv, g_qkv);
    cudaGetSymbolAddress((void**)&po,   g_o);
    cudaGetSymbolAddress((void**)&pxa,  g_xa);
    cudaGetSymbolAddress((void**)&py,   g_y);
    cudaGetSymbolAddress((void**)&pu,   g_u);

    // 1. LN1 + shift + window-partition gather
    ln_kernel<1><<<TOK, 128>>>(x, ln1_g, ln1_b, ph);

    // 2. qkv = h @ qkv_w + qkv_b       [100352 x 1152]
    sgemm_k<0><<<dim3(1152 / 128, TOK / 128), 256>>>(ph, qkv_w, qkv_b, nullptr, pqkv, 1152, 384);

    // 3. windowed attention
    attn_kernel<<<2048 * NHEAD, 256>>>(pqkv, bias_tb, po);

    // 4. proj + window-reverse/unshift scatter + residual with input x
    sgemm_k<3><<<dim3(384 / 128, TOK / 128), 256>>>(po, proj_w, proj_b, x, pxa, 384, 384);

    // 5. LN2
    ln_kernel<0><<<TOK, 128>>>(pxa, ln2_g, ln2_b, py);

    // 6. fc1 + exact gelu              [100352 x 1536]
    sgemm_k<1><<<dim3(1536 / 128, TOK / 128), 256>>>(py, fc1_w, fc1_b, nullptr, pu, 1536, 384);

    // 7. fc2 + residual -> out
    sgemm_k<2><<<dim3(384 / 128, TOK / 128), 256>>>(pu, fc2_w, fc2_b, pxa, out, 384, 1536);
}

// round 4
// speedup vs baseline: 2.2489x; 2.2489x over previous
#include <cuda_runtime.h>
#include <math.h>
#include <stdint.h>

// ---------------- problem constants ----------------
#define CDIM    384
#define NHEAD   12
#define TOK     100352        // 32*3136
#define EPS     1e-5f
#define SCALE   0.17677669529663687f  // 1/sqrt(32)

// ---------------- scratch (device globals; no allocations) ----------------
__device__ float g_h  [(size_t)TOK * 384];
__device__ float g_qkv[(size_t)TOK * 1152];
__device__ float g_o  [(size_t)TOK * 384];
__device__ float g_xa [(size_t)TOK * 384];
__device__ float g_y  [(size_t)TOK * 384];
__device__ float g_u  [(size_t)TOK * 1536];
__device__ float g_wt [1769472];              // transposed+rounded weights

#define WT_QKV 0
#define WT_PROJ 442368
#define WT_FC1 589824
#define WT_FC2 1179648

// ---------------- small PTX helpers ----------------
__device__ __forceinline__ uint32_t smem_u32(const void* p){
    uint32_t a;
    asm("{ .reg .u64 t; cvta.to.shared.u64 t, %1; cvt.u32.u64 %0, t; }" : "=r"(a) : "l"(p));
    return a;
}
__device__ __forceinline__ float tf32r(float f){
    uint32_t r; asm("cvt.rna.tf32.f32 %0, %1;" : "=r"(r) : "f"(f));
    return __uint_as_float(r);
}
__device__ __forceinline__ void cp16(uint32_t d, const void* s){
    asm volatile("cp.async.cg.shared.global [%0], [%1], 16;" :: "r"(d), "l"(s));
}
__device__ __forceinline__ void cp_commit(){ asm volatile("cp.async.commit_group;"); }
__device__ __forceinline__ void cp_wait1(){ asm volatile("cp.async.wait_group 1;" ::: "memory"); }
__device__ __forceinline__ void cp_wait0(){ asm volatile("cp.async.wait_group 0;" ::: "memory"); }

// tf32 m16n8k8 mma: D += A*B  (A row-major 16x8, B col-major 8x8)
__device__ __forceinline__ void mma8(float* d, const float* a, float b0, float b1){
    asm volatile("mma.sync.aligned.m16n8k8.row.col.f32.tf32.tf32.f32 "
        "{%0,%1,%2,%3}, {%4,%5,%6,%7}, {%8,%9}, {%0,%1,%2,%3};"
        : "+f"(d[0]), "+f"(d[1]), "+f"(d[2]), "+f"(d[3])
        : "r"(__float_as_uint(a[0])), "r"(__float_as_uint(a[1])),
          "r"(__float_as_uint(a[2])), "r"(__float_as_uint(a[3])),
          "r"(__float_as_uint(b0)),  "r"(__float_as_uint(b1)));
}

// window-order row t <-> original-order row (self-inverse map)
__device__ __forceinline__ int winrow_to_orig(int t) {
    int b   = t / 3136;
    int rem = t - b * 3136;
    int w   = rem / 49;
    int n   = rem - w * 49;
    int wr = w >> 3, wc = w & 7;
    int r  = n / 7,  c  = n - r * 7;
    int gh = wr * 7 + r + 3; if (gh >= 56) gh -= 56;
    int gw = wc * 7 + c + 3; if (gw >= 56) gw -= 56;
    return b * 3136 + gh * 56 + gw;
}

// ---------------- LayerNorm (outputs TF32-rounded; optional window gather) --
template<int GATHER>
__global__ void __launch_bounds__(128) ln_kernel(
    const float* __restrict__ x, const float* __restrict__ g,
    const float* __restrict__ b, float* __restrict__ out)
{
    int t   = blockIdx.x;
    int src = GATHER ? winrow_to_orig(t) : t;
    const float* xr = x + (size_t)src * CDIM;
    int tid = threadIdx.x;

    float v0 = xr[tid], v1 = xr[tid + 128], v2 = xr[tid + 256];
    float s  = v0 + v1 + v2;
    float sq = v0 * v0 + v1 * v1 + v2 * v2;

    __shared__ float rs[128], rq[128];
    rs[tid] = s; rq[tid] = sq;
    __syncthreads();
    #pragma unroll
    for (int off = 64; off > 0; off >>= 1) {
        if (tid < off) { rs[tid] += rs[tid + off]; rq[tid] += rq[tid + off]; }
        __syncthreads();
    }
    float mean = rs[0] * (1.0f / CDIM);
    float var  = rq[0] * (1.0f / CDIM) - mean * mean;
    float inv  = rsqrtf(var + EPS);

    float* orow = out + (size_t)t * CDIM;
    orow[tid      ] = tf32r((v0 - mean) * inv * g[tid      ] + b[tid      ]);
    orow[tid + 128] = tf32r((v1 - mean) * inv * g[tid + 128] + b[tid + 128]);
    orow[tid + 256] = tf32r((v2 - mean) * inv * g[tid + 256] + b[tid + 256]);
}

// ---------------- weight transpose + TF32 round:  in[K,N] -> out[N,K] ------
__global__ void __launch_bounds__(256) transpose_round(
    const float* __restrict__ in, float* __restrict__ out, int K, int N)
{
    __shared__ float tile[32][33];
    int k0 = blockIdx.y * 32, n0 = blockIdx.x * 32;
    int tx = threadIdx.x, ty = threadIdx.y;
    #pragma unroll
    for (int i = ty; i < 32; i += 8)
        tile[i][tx] = in[(size_t)(k0 + i) * N + n0 + tx];
    __syncthreads();
    #pragma unroll
    for (int i = ty; i < 32; i += 8)
        out[(size_t)(n0 + i) * K + k0 + tx] = tf32r(tile[tx][i]);
}

// ---------------- TF32 mma.sync GEMM, 128x128 tile, K staged by 32 ---------
// A: [M,K] row-major (tf32-rounded), Bt: [N,K] row-major (tf32-rounded)
// MODE 0: C = A*Bt' + bias
// MODE 1: C = tf32r(gelu(A*Bt' + bias))
// MODE 2: C = A*Bt' + bias + res
// MODE 3: C[map(row)] = A*Bt' + bias + res[map(row)]
// smem: 2 stages x (A 128x36 + B 128x36) floats = 73728 B
#define STG_F   9216     // floats per stage
#define SMEM_SZ 73728

template<int MODE>
__global__ void __launch_bounds__(256, 2) tc_gemm(
    const float* __restrict__ A, const float* __restrict__ Bt,
    const float* __restrict__ bias, const float* __restrict__ res,
    float* __restrict__ C, int N, int K)
{
    extern __shared__ float smem[];
    int tid  = threadIdx.x;
    int lane = tid & 31;
    int wid  = tid >> 5;
    int warp_m = wid & 1;          // 2 x 64 rows
    int warp_n = wid >> 1;         // 4 x 32 cols
    int m0 = blockIdx.y << 7, n0 = blockIdx.x << 7;

    const float* Arow = A  + (size_t)m0 * K;
    const float* Brow = Bt + (size_t)n0 * K;
    const int nst = K >> 5;

    uint32_t sbase = smem_u32(smem);

    // each thread: 4 (A cp16 + B cp16) pairs per stage
    int ldrow = tid >> 3;          // 0..31  (row group of 4: p adds 32)
    int ldc4  = tid & 7;           // 16B chunk within 32-float row

    auto issue_stage = [&](int s, int buf) {
        int kt = s << 5;
        uint32_t bA = sbase + (uint32_t)buf * (STG_F * 4);
        uint32_t bB = bA + 4608 * 4;
        #pragma unroll
        for (int p = 0; p < 4; ++p) {
            int row = ldrow + (p << 5);
            uint32_t doff = (uint32_t)row * 144 + (uint32_t)(ldc4 << 4);
            cp16(bA + doff, Arow + (size_t)row * K + kt + (ldc4 << 2));
            cp16(bB + doff, Brow + (size_t)row * K + kt + (ldc4 << 2));
        }
        cp_commit();
    };

    float acc[4][4][4];
    #pragma unroll
    for (int i = 0; i < 4; i++)
        #pragma unroll
        for (int j = 0; j < 4; j++)
            #pragma unroll
            for (int r = 0; r < 4; r++) acc[i][j][r] = 0.0f;

    issue_stage(0, 0);

    int lr = lane >> 2;            // 0..7
    int lc = lane & 3;             // 0..3

    for (int s = 0; s < nst; ++s) {
        int buf = s & 1;
        __syncthreads();                        // prev compute done before overwrite
        if (s + 1 < nst) { issue_stage(s + 1, buf ^ 1); cp_wait1(); }
        else             { cp_wait0(); }
        __syncthreads();                        // stage s visible to all

        const float* As = smem + buf * STG_F;
        const float* Bs = As + 4608;

        #pragma unroll
        for (int kk = 0; kk < 32; kk += 8) {
            float a[4][4];
            #pragma unroll
            for (int mt = 0; mt < 4; mt++) {
                int r = (warp_m << 6) + (mt << 4) + lr;
                a[mt][0] = As[r * 36 + kk + lc];
                a[mt][1] = As[(r + 8) * 36 + kk + lc];
                a[mt][2] = As[r * 36 + kk + 4 + lc];
                a[mt][3] = As[(r + 8) * 36 + kk + 4 + lc];
            }
            #pragma unroll
            for (int nt = 0; nt < 4; nt++) {
                int c = (warp_n << 5) + (nt << 3) + lr;
                float b0 = Bs[c * 36 + kk + lc];
                float b1 = Bs[c * 36 + kk + 4 + lc];
                #pragma unroll
                for (int mt = 0; mt < 4; mt++)
                    mma8(acc[mt][nt], a[mt], b0, b1);
            }
        }
    }

    // ---- epilogue ----
    #pragma unroll
    for (int mt = 0; mt < 4; mt++) {
        #pragma unroll
        for (int h = 0; h < 2; h++) {
            int row  = m0 + (warp_m << 6) + (mt << 4) + lr + (h << 3);
            int orow = (MODE == 3) ? winrow_to_orig(row) : row;
            float* dst = C + (size_t)orow * N + n0 + (warp_n << 5);
            const float* rp = (MODE >= 2) ? (res + (size_t)orow * N + n0 + (warp_n << 5))
                                          : (const float*)0;
            #pragma unroll
            for (int nt = 0; nt < 4; nt++) {
                int c = (nt << 3) + (lc << 1);
                float2 bv = *(const float2*)(bias + n0 + (warp_n << 5) + c);
                float v0 = acc[mt][nt][h * 2 + 0] + bv.x;
                float v1 = acc[mt][nt][h * 2 + 1] + bv.y;
                if (MODE == 1) {
                    v0 = tf32r(0.5f * v0 * (1.0f + erff(v0 * 0.70710678118654752f)));
                    v1 = tf32r(0.5f * v1 * (1.0f + erff(v1 * 0.70710678118654752f)));
                } else if (MODE >= 2) {
                    float2 rv = *(const float2*)(rp + c);
                    v0 += rv.x; v1 += rv.y;
                }
                float2 o; o.x = v0; o.y = v1;
                *(float2*)(dst + c) = o;
            }
        }
    }
}

// ---------------- attention: one block per (window, head) ------------------
__device__ __forceinline__ int regio(int g) { return g < 49 ? 0 : (g < 53 ? 1 : 2); }

__global__ void __launch_bounds__(256) attn_kernel(
    const float* __restrict__ qkv, const float* __restrict__ bias_table,
    float* __restrict__ o)
{
    int bh   = blockIdx.x;
    int wi   = bh / NHEAD;
    int head = bh - wi * NHEAD;
    int w    = wi & 63;
    int tid  = threadIdx.x;

    __shared__ float qs[49][32];
    __shared__ float ks[49][32];
    __shared__ float vs[49][32];
    __shared__ float S [49][49];

    size_t base = (size_t)wi * 49 * 1152 + head * 32;
    for (int e = tid; e < 49 * 32; e += 256) {
        int n = e >> 5, d = e & 31;
        size_t off = base + (size_t)n * 1152 + d;
        qs[n][d] = qkv[off] * SCALE;
        ks[n][d] = qkv[off + 384];
        vs[n][d] = qkv[off + 768];
    }
    __syncthreads();

    int wr = w >> 3, wc = w & 7;
    for (int e = tid; e < 49 * 49; e += 256) {
        int i = e / 49, j = e - i * 49;
        float s = 0.0f;
        #pragma unroll
        for (int d = 0; d < 32; d++) s += qs[i][d] * ks[j][d];

        int ih = i / 7, iw = i - ih * 7;
        int jh = j / 7, jw = j - jh * 7;
        int ridx = (ih - jh + 6) * 13 + (iw - jw + 6);
        s += bias_table[ridx * NHEAD + head];

        int li = regio(wr * 7 + ih) * 3 + regio(wc * 7 + iw);
        int lj = regio(wr * 7 + jh) * 3 + regio(wc * 7 + jw);
        if (li != lj) s -= 100.0f;
        S[i][j] = s;
    }
    __syncthreads();

    if (tid < 49) {
        float mx = -1e30f;
        #pragma unroll 7
        for (int j = 0; j < 49; j++) mx = fmaxf(mx, S[tid][j]);
        float sm = 0.0f;
        #pragma unroll 7
        for (int j = 0; j < 49; j++) {
            float e = __expf(S[tid][j] - mx);
            S[tid][j] = e; sm += e;
        }
        float inv = 1.0f / sm;
        #pragma unroll 7
        for (int j = 0; j < 49; j++) S[tid][j] *= inv;
    }
    __syncthreads();

    for (int e = tid; e < 49 * 32; e += 256) {
        int i = e >> 5, d = e & 31;
        float s = 0.0f;
        #pragma unroll 7
        for (int j = 0; j < 49; j++) s += S[i][j] * vs[j][d];
        o[(size_t)wi * 49 * 384 + (size_t)i * 384 + head * 32 + d] = tf32r(s);
    }
}

// ---------------- host launch ----------------------------------------------
extern "C" void kernel_launch(void* const* d_in, const int* in_sizes, int n_in,
                              void* d_out, int out_size)
{
    const float* x       = (const float*)d_in[0];
    const float* ln1_g   = (const float*)d_in[1];
    const float* ln1_b   = (const float*)d_in[2];
    const float* qkv_w   = (const float*)d_in[3];
    const float* qkv_b   = (const float*)d_in[4];
    const float* proj_w  = (const float*)d_in[5];
    const float* proj_b  = (const float*)d_in[6];
    const float* bias_tb = (const float*)d_in[7];
    const float* ln2_g   = (const float*)d_in[8];
    const float* ln2_b   = (const float*)d_in[9];
    const float* fc1_w   = (const float*)d_in[10];
    const float* fc1_b   = (const float*)d_in[11];
    const float* fc2_w   = (const float*)d_in[12];
    const float* fc2_b   = (const float*)d_in[13];
    float*       out     = (float*)d_out;

    float *ph, *pqkv, *po, *pxa, *py, *pu, *pwt;
    cudaGetSymbolAddress((void**)&ph,   g_h);
    cudaGetSymbolAddress((void**)&pqkv, g_qkv);
    cudaGetSymbolAddress((void**)&po,   g_o);
    cudaGetSymbolAddress((void**)&pxa,  g_xa);
    cudaGetSymbolAddress((void**)&py,   g_y);
    cudaGetSymbolAddress((void**)&pu,   g_u);
    cudaGetSymbolAddress((void**)&pwt,  g_wt);

    cudaFuncSetAttribute(tc_gemm<0>, cudaFuncAttributeMaxDynamicSharedMemorySize, SMEM_SZ);
    cudaFuncSetAttribute(tc_gemm<1>, cudaFuncAttributeMaxDynamicSharedMemorySize, SMEM_SZ);
    cudaFuncSetAttribute(tc_gemm<2>, cudaFuncAttributeMaxDynamicSharedMemorySize, SMEM_SZ);
    cudaFuncSetAttribute(tc_gemm<3>, cudaFuncAttributeMaxDynamicSharedMemorySize, SMEM_SZ);

    // 0. weight transpose + tf32 round
    dim3 tb(32, 8);
    transpose_round<<<dim3(1152 / 32,  384 / 32), tb>>>(qkv_w,  pwt + WT_QKV,  384, 1152);
    transpose_round<<<dim3( 384 / 32,  384 / 32), tb>>>(proj_w, pwt + WT_PROJ, 384,  384);
    transpose_round<<<dim3(1536 / 32,  384 / 32), tb>>>(fc1_w,  pwt + WT_FC1,  384, 1536);
    transpose_round<<<dim3( 384 / 32, 1536 / 32), tb>>>(fc2_w,  pwt + WT_FC2, 1536,  384);

    // 1. LN1 + shift + window gather (tf32-rounded)
    ln_kernel<1><<<TOK, 128>>>(x, ln1_g, ln1_b, ph);

    // 2. qkv GEMM [100352 x 1152], K=384
    tc_gemm<0><<<dim3(9, TOK / 128), 256, SMEM_SZ>>>(ph, pwt + WT_QKV, qkv_b, nullptr, pqkv, 1152, 384);

    // 3. windowed attention (output tf32-rounded)
    attn_kernel<<<2048 * NHEAD, 256>>>(pqkv, bias_tb, po);

    // 4. proj GEMM + window-reverse scatter + residual(x)
    tc_gemm<3><<<dim3(3, TOK / 128), 256, SMEM_SZ>>>(po, pwt + WT_PROJ, proj_b, x, pxa, 384, 384);

    // 5. LN2 (tf32-rounded)
    ln_kernel<0><<<TOK, 128>>>(pxa, ln2_g, ln2_b, py);

    // 6. fc1 GEMM + gelu (tf32-rounded), N=1536
    tc_gemm<1><<<dim3(12, TOK / 128), 256, SMEM_SZ>>>(py, pwt + WT_FC1, fc1_b, nullptr, pu, 1536, 384);

    // 7. fc2 GEMM + residual -> out, K=1536
    tc_gemm<2><<<dim3(3, TOK / 128), 256, SMEM_SZ>>>(pu, pwt + WT_FC2, fc2_b, pxa, out, 384, 1536);
}

// round 5
// speedup vs baseline: 3.1037x; 1.3801x over previous
#include <cuda_runtime.h>
#include <math.h>
#include <stdint.h>

// ---------------- problem constants ----------------
#define CDIM    384
#define NHEAD   12
#define TOK     100352        // 32*3136
#define EPS     1e-5f
#define SCALE   0.17677669529663687f  // 1/sqrt(32)

// ---------------- scratch (device globals; no allocations) ----------------
__device__ float g_h  [(size_t)TOK * 384];
__device__ float g_qkv[(size_t)TOK * 1152];
__device__ float g_o  [(size_t)TOK * 384];
__device__ float g_xa [(size_t)TOK * 384];
__device__ float g_y  [(size_t)TOK * 384];
__device__ float g_u  [(size_t)TOK * 1536];
__device__ float g_wt [1769472];              // transposed+rounded weights

#define WT_QKV 0
#define WT_PROJ 442368
#define WT_FC1 589824
#define WT_FC2 1179648

// ---------------- small PTX helpers ----------------
__device__ __forceinline__ uint32_t smem_u32(const void* p){
    uint32_t a;
    asm("{ .reg .u64 t; cvta.to.shared.u64 t, %1; cvt.u32.u64 %0, t; }" : "=r"(a) : "l"(p));
    return a;
}
__device__ __forceinline__ float tf32r(float f){
    uint32_t r; asm("cvt.rna.tf32.f32 %0, %1;" : "=r"(r) : "f"(f));
    return __uint_as_float(r);
}
__device__ __forceinline__ void cp16(uint32_t d, const void* s){
    asm volatile("cp.async.cg.shared.global [%0], [%1], 16;" :: "r"(d), "l"(s));
}
__device__ __forceinline__ void cp_commit(){ asm volatile("cp.async.commit_group;"); }
__device__ __forceinline__ void cp_wait1(){ asm volatile("cp.async.wait_group 1;" ::: "memory"); }
__device__ __forceinline__ void cp_wait0(){ asm volatile("cp.async.wait_group 0;" ::: "memory"); }

// tf32 m16n8k8 mma: D += A*B  (A row-major 16x8, B col-major 8x8)
__device__ __forceinline__ void mma8(float* d, const float* a, float b0, float b1){
    asm volatile("mma.sync.aligned.m16n8k8.row.col.f32.tf32.tf32.f32 "
        "{%0,%1,%2,%3}, {%4,%5,%6,%7}, {%8,%9}, {%0,%1,%2,%3};"
        : "+f"(d[0]), "+f"(d[1]), "+f"(d[2]), "+f"(d[3])
        : "r"(__float_as_uint(a[0])), "r"(__float_as_uint(a[1])),
          "r"(__float_as_uint(a[2])), "r"(__float_as_uint(a[3])),
          "r"(__float_as_uint(b0)),  "r"(__float_as_uint(b1)));
}

// window-order row t <-> original-order row (self-inverse map)
__device__ __forceinline__ int winrow_to_orig(int t) {
    int b   = t / 3136;
    int rem = t - b * 3136;
    int w   = rem / 49;
    int n   = rem - w * 49;
    int wr = w >> 3, wc = w & 7;
    int r  = n / 7,  c  = n - r * 7;
    int gh = wr * 7 + r + 3; if (gh >= 56) gh -= 56;
    int gw = wc * 7 + c + 3; if (gw >= 56) gw -= 56;
    return b * 3136 + gh * 56 + gw;
}

// ---------------- LayerNorm (outputs TF32-rounded; optional window gather) --
template<int GATHER>
__global__ void __launch_bounds__(128) ln_kernel(
    const float* __restrict__ x, const float* __restrict__ g,
    const float* __restrict__ b, float* __restrict__ out)
{
    int t   = blockIdx.x;
    int src = GATHER ? winrow_to_orig(t) : t;
    const float* xr = x + (size_t)src * CDIM;
    int tid = threadIdx.x;

    float v0 = xr[tid], v1 = xr[tid + 128], v2 = xr[tid + 256];
    float s  = v0 + v1 + v2;
    float sq = v0 * v0 + v1 * v1 + v2 * v2;

    __shared__ float rs[128], rq[128];
    rs[tid] = s; rq[tid] = sq;
    __syncthreads();
    #pragma unroll
    for (int off = 64; off > 0; off >>= 1) {
        if (tid < off) { rs[tid] += rs[tid + off]; rq[tid] += rq[tid + off]; }
        __syncthreads();
    }
    float mean = rs[0] * (1.0f / CDIM);
    float var  = rq[0] * (1.0f / CDIM) - mean * mean;
    float inv  = rsqrtf(var + EPS);

    float* orow = out + (size_t)t * CDIM;
    orow[tid      ] = tf32r((v0 - mean) * inv * g[tid      ] + b[tid      ]);
    orow[tid + 128] = tf32r((v1 - mean) * inv * g[tid + 128] + b[tid + 128]);
    orow[tid + 256] = tf32r((v2 - mean) * inv * g[tid + 256] + b[tid + 256]);
}

// ---------------- weight transpose + TF32 round:  in[K,N] -> out[N,K] ------
__global__ void __launch_bounds__(256) transpose_round(
    const float* __restrict__ in, float* __restrict__ out, int K, int N)
{
    __shared__ float tile[32][33];
    int k0 = blockIdx.y * 32, n0 = blockIdx.x * 32;
    int tx = threadIdx.x, ty = threadIdx.y;
    #pragma unroll
    for (int i = ty; i < 32; i += 8)
        tile[i][tx] = in[(size_t)(k0 + i) * N + n0 + tx];
    __syncthreads();
    #pragma unroll
    for (int i = ty; i < 32; i += 8)
        out[(size_t)(n0 + i) * K + k0 + tx] = tf32r(tile[tx][i]);
}

// ---------------- TF32 mma.sync GEMM, 128x128 tile, K staged by 32 ---------
// A: [M,K] row-major (tf32-rounded), Bt: [N,K] row-major (tf32-rounded)
// MODE 0: C = A*Bt' + bias
// MODE 1: C = tf32r(gelu(A*Bt' + bias))
// MODE 2: C = A*Bt' + bias + res
// MODE 3: C[map(row)] = A*Bt' + bias + res[map(row)]
#define STG_F   9216     // floats per stage
#define SMEM_SZ 73728

template<int MODE>
__global__ void __launch_bounds__(256, 2) tc_gemm(
    const float* __restrict__ A, const float* __restrict__ Bt,
    const float* __restrict__ bias, const float* __restrict__ res,
    float* __restrict__ C, int N, int K)
{
    extern __shared__ float smem[];
    int tid  = threadIdx.x;
    int lane = tid & 31;
    int wid  = tid >> 5;
    int warp_m = wid & 1;          // 2 x 64 rows
    int warp_n = wid >> 1;         // 4 x 32 cols
    int m0 = blockIdx.y << 7, n0 = blockIdx.x << 7;

    const float* Arow = A  + (size_t)m0 * K;
    const float* Brow = Bt + (size_t)n0 * K;
    const int nst = K >> 5;

    uint32_t sbase = smem_u32(smem);

    int ldrow = tid >> 3;          // 0..31
    int ldc4  = tid & 7;           // 16B chunk within 32-float row

    auto issue_stage = [&](int s, int buf) {
        int kt = s << 5;
        uint32_t bA = sbase + (uint32_t)buf * (STG_F * 4);
        uint32_t bB = bA + 4608 * 4;
        #pragma unroll
        for (int p = 0; p < 4; ++p) {
            int row = ldrow + (p << 5);
            uint32_t doff = (uint32_t)row * 144 + (uint32_t)(ldc4 << 4);
            cp16(bA + doff, Arow + (size_t)row * K + kt + (ldc4 << 2));
            cp16(bB + doff, Brow + (size_t)row * K + kt + (ldc4 << 2));
        }
        cp_commit();
    };

    float acc[4][4][4];
    #pragma unroll
    for (int i = 0; i < 4; i++)
        #pragma unroll
        for (int j = 0; j < 4; j++)
            #pragma unroll
            for (int r = 0; r < 4; r++) acc[i][j][r] = 0.0f;

    issue_stage(0, 0);

    int lr = lane >> 2;            // 0..7
    int lc = lane & 3;             // 0..3

    for (int s = 0; s < nst; ++s) {
        int buf = s & 1;
        __syncthreads();
        if (s + 1 < nst) { issue_stage(s + 1, buf ^ 1); cp_wait1(); }
        else             { cp_wait0(); }
        __syncthreads();

        const float* As = smem + buf * STG_F;
        const float* Bs = As + 4608;

        #pragma unroll
        for (int kk = 0; kk < 32; kk += 8) {
            float a[4][4];
            #pragma unroll
            for (int mt = 0; mt < 4; mt++) {
                int r = (warp_m << 6) + (mt << 4) + lr;
                a[mt][0] = As[r * 36 + kk + lc];
                a[mt][1] = As[(r + 8) * 36 + kk + lc];
                a[mt][2] = As[r * 36 + kk + 4 + lc];
                a[mt][3] = As[(r + 8) * 36 + kk + 4 + lc];
            }
            #pragma unroll
            for (int nt = 0; nt < 4; nt++) {
                int c = (warp_n << 5) + (nt << 3) + lr;
                float b0 = Bs[c * 36 + kk + lc];
                float b1 = Bs[c * 36 + kk + 4 + lc];
                #pragma unroll
                for (int mt = 0; mt < 4; mt++)
                    mma8(acc[mt][nt], a[mt], b0, b1);
            }
        }
    }

    // ---- epilogue ----
    #pragma unroll
    for (int mt = 0; mt < 4; mt++) {
        #pragma unroll
        for (int h = 0; h < 2; h++) {
            int row  = m0 + (warp_m << 6) + (mt << 4) + lr + (h << 3);
            int orow = (MODE == 3) ? winrow_to_orig(row) : row;
            float* dst = C + (size_t)orow * N + n0 + (warp_n << 5);
            const float* rp = (MODE >= 2) ? (res + (size_t)orow * N + n0 + (warp_n << 5))
                                          : (const float*)0;
            #pragma unroll
            for (int nt = 0; nt < 4; nt++) {
                int c = (nt << 3) + (lc << 1);
                float2 bv = *(const float2*)(bias + n0 + (warp_n << 5) + c);
                float v0 = acc[mt][nt][h * 2 + 0] + bv.x;
                float v1 = acc[mt][nt][h * 2 + 1] + bv.y;
                if (MODE == 1) {
                    v0 = tf32r(0.5f * v0 * (1.0f + erff(v0 * 0.70710678118654752f)));
                    v1 = tf32r(0.5f * v1 * (1.0f + erff(v1 * 0.70710678118654752f)));
                } else if (MODE >= 2) {
                    float2 rv = *(const float2*)(rp + c);
                    v0 += rv.x; v1 += rv.y;
                }
                float2 o; o.x = v0; o.y = v1;
                *(float2*)(dst + c) = o;
            }
        }
    }
}

// ---------------- attention: one block per (window, head), conflict-free ---
__device__ __forceinline__ int regio(int g) { return g < 49 ? 0 : (g < 53 ? 1 : 2); }

__global__ void __launch_bounds__(256) attn_kernel(
    const float* __restrict__ qkv, const float* __restrict__ bias_table,
    float* __restrict__ o)
{
    int bh   = blockIdx.x;
    int wi   = bh / NHEAD;
    int head = bh - wi * NHEAD;
    int w    = wi & 63;
    int tid  = threadIdx.x;
    int lane = tid & 31;
    int wid  = tid >> 5;

    __shared__ float qs[49][36];
    __shared__ float ks[49][36];
    __shared__ float vs[49][36];
    __shared__ float S [49][49];

    // load q/k/v slices (rows stride 36 -> conflict-free everywhere below)
    size_t base = (size_t)wi * 49 * 1152 + head * 32;
    for (int e = tid; e < 49 * 32; e += 256) {
        int n = e >> 5, d = e & 31;
        size_t off = base + (size_t)n * 1152 + d;
        qs[n][d] = qkv[off] * SCALE;
        ks[n][d] = qkv[off + 384];
        vs[n][d] = qkv[off + 768];
    }
    __syncthreads();

    int wr = w >> 3, wc = w & 7;

    // QK^T + bias + mask + softmax: one warp per row i
    for (int i = wid; i < 49; i += 8) {
        float4 q[8];
        #pragma unroll
        for (int t = 0; t < 8; t++) q[t] = *(const float4*)&qs[i][t * 4];
        int ih = i / 7, iw = i - ih * 7;
        int li = regio(wr * 7 + ih) * 3 + regio(wc * 7 + iw);

        float sv0, sv1;
        {
            int j = lane;
            float s = 0.0f;
            #pragma unroll
            for (int t = 0; t < 8; t++) {
                float4 kv = *(const float4*)&ks[j][t * 4];
                s += q[t].x * kv.x + q[t].y * kv.y + q[t].z * kv.z + q[t].w * kv.w;
            }
            int jh = j / 7, jw = j - jh * 7;
            s += bias_table[((ih - jh + 6) * 13 + (iw - jw + 6)) * NHEAD + head];
            int lj = regio(wr * 7 + jh) * 3 + regio(wc * 7 + jw);
            if (li != lj) s -= 100.0f;
            sv0 = s;
        }
        if (lane < 17) {
            int j = lane + 32;
            float s = 0.0f;
            #pragma unroll
            for (int t = 0; t < 8; t++) {
                float4 kv = *(const float4*)&ks[j][t * 4];
                s += q[t].x * kv.x + q[t].y * kv.y + q[t].z * kv.z + q[t].w * kv.w;
            }
            int jh = j / 7, jw = j - jh * 7;
            s += bias_table[((ih - jh + 6) * 13 + (iw - jw + 6)) * NHEAD + head];
            int lj = regio(wr * 7 + jh) * 3 + regio(wc * 7 + jw);
            if (li != lj) s -= 100.0f;
            sv1 = s;
        } else sv1 = -1e30f;

        // warp softmax over 49 values
        float mx = fmaxf(sv0, sv1);
        #pragma unroll
        for (int off = 16; off; off >>= 1) mx = fmaxf(mx, __shfl_xor_sync(~0u, mx, off));
        float e0 = __expf(sv0 - mx);
        float e1 = (lane < 17) ? __expf(sv1 - mx) : 0.0f;
        float sm = e0 + e1;
        #pragma unroll
        for (int off = 16; off; off >>= 1) sm += __shfl_xor_sync(~0u, sm, off);
        float inv = 1.0f / sm;
        S[i][lane] = e0 * inv;
        if (lane < 17) S[i][lane + 32] = e1 * inv;
    }
    __syncthreads();

    // AV: thread = (row i, d-quad)
    size_t obase = (size_t)wi * 49 * 384 + head * 32;
    for (int task = tid; task < 49 * 8; task += 256) {
        int i = task >> 3, d4 = task & 7;
        float ax = 0.f, ay = 0.f, az = 0.f, aw = 0.f;
        #pragma unroll 7
        for (int j = 0; j < 49; j++) {
            float s = S[i][j];
            float4 v = *(const float4*)&vs[j][d4 * 4];
            ax += s * v.x; ay += s * v.y; az += s * v.z; aw += s * v.w;
        }
        float4 r;
        r.x = tf32r(ax); r.y = tf32r(ay); r.z = tf32r(az); r.w = tf32r(aw);
        *(float4*)&o[obase + (size_t)i * 384 + d4 * 4] = r;
    }
}

// ---------------- host launch ----------------------------------------------
extern "C" void kernel_launch(void* const* d_in, const int* in_sizes, int n_in,
                              void* d_out, int out_size)
{
    const float* x       = (const float*)d_in[0];
    const float* ln1_g   = (const float*)d_in[1];
    const float* ln1_b   = (const float*)d_in[2];
    const float* qkv_w   = (const float*)d_in[3];
    const float* qkv_b   = (const float*)d_in[4];
    const float* proj_w  = (const float*)d_in[5];
    const float* proj_b  = (const float*)d_in[6];
    const float* bias_tb = (const float*)d_in[7];
    const float* ln2_g   = (const float*)d_in[8];
    const float* ln2_b   = (const float*)d_in[9];
    const float* fc1_w   = (const float*)d_in[10];
    const float* fc1_b   = (const float*)d_in[11];
    const float* fc2_w   = (const float*)d_in[12];
    const float* fc2_b   = (const float*)d_in[13];
    float*       out     = (float*)d_out;

    float *ph, *pqkv, *po, *pxa, *py, *pu, *pwt;
    cudaGetSymbolAddress((void**)&ph,   g_h);
    cudaGetSymbolAddress((void**)&pqkv, g_qkv);
    cudaGetSymbolAddress((void**)&po,   g_o);
    cudaGetSymbolAddress((void**)&pxa,  g_xa);
    cudaGetSymbolAddress((void**)&py,   g_y);
    cudaGetSymbolAddress((void**)&pu,   g_u);
    cudaGetSymbolAddress((void**)&pwt,  g_wt);

    cudaFuncSetAttribute(tc_gemm<0>, cudaFuncAttributeMaxDynamicSharedMemorySize, SMEM_SZ);
    cudaFuncSetAttribute(tc_gemm<1>, cudaFuncAttributeMaxDynamicSharedMemorySize, SMEM_SZ);
    cudaFuncSetAttribute(tc_gemm<2>, cudaFuncAttributeMaxDynamicSharedMemorySize, SMEM_SZ);
    cudaFuncSetAttribute(tc_gemm<3>, cudaFuncAttributeMaxDynamicSharedMemorySize, SMEM_SZ);

    // 0. weight transpose + tf32 round
    dim3 tb(32, 8);
    transpose_round<<<dim3(1152 / 32,  384 / 32), tb>>>(qkv_w,  pwt + WT_QKV,  384, 1152);
    transpose_round<<<dim3( 384 / 32,  384 / 32), tb>>>(proj_w, pwt + WT_PROJ, 384,  384);
    transpose_round<<<dim3(1536 / 32,  384 / 32), tb>>>(fc1_w,  pwt + WT_FC1,  384, 1536);
    transpose_round<<<dim3( 384 / 32, 1536 / 32), tb>>>(fc2_w,  pwt + WT_FC2, 1536,  384);

    // 1. LN1 + shift + window gather (tf32-rounded)
    ln_kernel<1><<<TOK, 128>>>(x, ln1_g, ln1_b, ph);

    // 2. qkv GEMM [100352 x 1152], K=384
    tc_gemm<0><<<dim3(9, TOK / 128), 256, SMEM_SZ>>>(ph, pwt + WT_QKV, qkv_b, nullptr, pqkv, 1152, 384);

    // 3. windowed attention (output tf32-rounded)
    attn_kernel<<<2048 * NHEAD, 256>>>(pqkv, bias_tb, po);

    // 4. proj GEMM + window-reverse scatter + residual(x)
    tc_gemm<3><<<dim3(3, TOK / 128), 256, SMEM_SZ>>>(po, pwt + WT_PROJ, proj_b, x, pxa, 384, 384);

    // 5. LN2 (tf32-rounded)
    ln_kernel<0><<<TOK, 128>>>(pxa, ln2_g, ln2_b, py);

    // 6. fc1 GEMM + gelu (tf32-rounded), N=1536
    tc_gemm<1><<<dim3(12, TOK / 128), 256, SMEM_SZ>>>(py, pwt + WT_FC1, fc1_b, nullptr, pu, 1536, 384);

    // 7. fc2 GEMM + residual -> out, K=1536
    tc_gemm<2><<<dim3(3, TOK / 128), 256, SMEM_SZ>>>(pu, pwt + WT_FC2, fc2_b, pxa, out, 384, 1536);
}